// round 2
// baseline (speedup 1.0000x reference)
#include <cuda_runtime.h>
#include <cstdint>

// Problem constants
#define kN 50000
#define kE 1600000
#define kR 8
#define kH 8
#define kDK 16
#define kD 128   // IN_DIM == OUT_DIM

// ---------------- scratch layout (single __device__ pool) ----------------
// floats:
//  q    @ 0          (6.4M)
//  k    @ 6.4M       (6.4M)
//  v    @ 12.8M      (6.4M)
//  t    @ 19.2M      (6.4M)
//  att  @ 25.6M      (12.8M)   [E*H]
//  den  @ 38.4M      (3.2M)    [N*R*H]
//  m    @ 41.6M      (3.2M)    [N*R*H]  (encoded uint)
//  ninv @ 44.8M      (50k)
//  krel @ 44.85M     (51.2M)   [R,N,128]
//  vrel @ 96.05M     (51.2M)
#define OFF_Q    0ull
#define OFF_K    6400000ull
#define OFF_V    12800000ull
#define OFF_T    19200000ull
#define OFF_ATT  25600000ull
#define OFF_DEN  38400000ull
#define OFF_M    41600000ull
#define OFF_NINV 44800000ull
#define OFF_KREL 44850000ull
#define OFF_VREL 96050000ull
#define POOL_SZ  147250000ull

__device__ float g_pool[POOL_SZ];

// ---------------- helpers ----------------
__device__ __forceinline__ unsigned enc_f(float f) {
    unsigned u = __float_as_uint(f);
    return (u & 0x80000000u) ? ~u : (u | 0x80000000u);
}
__device__ __forceinline__ float dec_f(unsigned u) {
    u = (u & 0x80000000u) ? (u & 0x7FFFFFFFu) : ~u;
    return __uint_as_float(u);
}
__device__ __forceinline__ void red_add_v4(float* p, float4 v) {
    asm volatile("red.global.add.v4.f32 [%0], {%1,%2,%3,%4};"
                 :: "l"(p), "f"(v.x), "f"(v.y), "f"(v.z), "f"(v.w) : "memory");
}

// ---------------- zero scratch (t, den, m) ----------------
__global__ void zero_kernel(float* __restrict__ t, float* __restrict__ denm) {
    // t: 6.4M floats ; denm: den+m contiguous 6.4M words
    size_t i = (size_t)blockIdx.x * blockDim.x + threadIdx.x;
    if (i < 6400000ull) { t[i] = 0.f; denm[i] = 0.f; }
}

// ---------------- SIMT sgemm: C[n,128] = A[n,128] @ W[128,128]^T + bias ----
// fuse==1: C = alpha*(AB^T+bias) + (1-alpha)*S,  alpha = sigmoid(skip[0])
__global__ __launch_bounds__(256) void gemm_out128(
    const float* __restrict__ A, const float* __restrict__ W,
    const float* __restrict__ bias, const float* __restrict__ S,
    const float* __restrict__ skipv, float* __restrict__ C,
    int n, int fuse)
{
    __shared__ float As[8][128];
    __shared__ float Bs[8][128];
    int row0 = blockIdx.x * 128;
    int tid = threadIdx.x;
    int tr = (tid >> 4) << 3;   // row offset in tile, 0..120
    int tc = (tid & 15) << 3;   // col offset
    float acc[8][8];
#pragma unroll
    for (int i = 0; i < 8; i++)
#pragma unroll
        for (int j = 0; j < 8; j++) acc[i][j] = 0.f;

    int li = tid >> 1;
    int lk = (tid & 1) << 2;
    for (int k0 = 0; k0 < 128; k0 += 8) {
        float4 a4 = make_float4(0.f, 0.f, 0.f, 0.f);
        if (row0 + li < n)
            a4 = *(const float4*)(A + (size_t)(row0 + li) * 128 + k0 + lk);
        As[lk + 0][li] = a4.x; As[lk + 1][li] = a4.y;
        As[lk + 2][li] = a4.z; As[lk + 3][li] = a4.w;
        float4 b4 = *(const float4*)(W + (size_t)li * 128 + k0 + lk);
        Bs[lk + 0][li] = b4.x; Bs[lk + 1][li] = b4.y;
        Bs[lk + 2][li] = b4.z; Bs[lk + 3][li] = b4.w;
        __syncthreads();
#pragma unroll
        for (int kk = 0; kk < 8; kk++) {
            float ar[8], br[8];
#pragma unroll
            for (int i = 0; i < 8; i++) ar[i] = As[kk][tr + i];
#pragma unroll
            for (int j = 0; j < 8; j++) br[j] = Bs[kk][tc + j];
#pragma unroll
            for (int i = 0; i < 8; i++)
#pragma unroll
                for (int j = 0; j < 8; j++) acc[i][j] += ar[i] * br[j];
        }
        __syncthreads();
    }
    float alpha = 1.f, beta = 0.f;
    if (fuse) {
        float sv = skipv[0];
        alpha = 1.f / (1.f + expf(-sv));
        beta = 1.f - alpha;
    }
#pragma unroll
    for (int i = 0; i < 8; i++) {
        int r = row0 + tr + i;
        if (r >= n) break;
#pragma unroll
        for (int j = 0; j < 8; j++) {
            int c = tc + j;
            float val = acc[i][j] + bias[c];
            if (fuse) val = alpha * val + beta * S[(size_t)r * 128 + c];
            C[(size_t)r * 128 + c] = val;
        }
    }
}

// ---------------- relation transforms: krel/vrel [R,N,128] ----------------
#define RT_TILE 32
__global__ __launch_bounds__(256) void rel_transform(
    const float* __restrict__ k, const float* __restrict__ v,
    const float* __restrict__ ratt, const float* __restrict__ rmsg,
    float* __restrict__ krel, float* __restrict__ vrel, int n)
{
    __shared__ float ks[RT_TILE][128];
    __shared__ float vs[RT_TILE][128];
    __shared__ float ma[2048];   // rel_att[r]: [h][d][e]
    __shared__ float mm[2048];
    int node0 = blockIdx.x * RT_TILE;
    int tid = threadIdx.x;
    for (int i = tid; i < RT_TILE * 32; i += 256) {  // float4 granularity
        int nd = i >> 5, c4 = i & 31;
        if (node0 + nd < n) {
            ((float4*)ks[nd])[c4] = ((const float4*)(k + (size_t)(node0 + nd) * 128))[c4];
            ((float4*)vs[nd])[c4] = ((const float4*)(v + (size_t)(node0 + nd) * 128))[c4];
        }
    }
    int c = tid & 127;
    int half = tid >> 7;
    int h = c >> 4, eo = c & 15;
    for (int r = 0; r < kR; r++) {
        __syncthreads();
        for (int i = tid; i < 2048; i += 256) {
            ma[i] = ratt[r * 2048 + i];
            mm[i] = rmsg[r * 2048 + i];
        }
        __syncthreads();
        for (int nd = half; nd < RT_TILE; nd += 2) {
            int gn = node0 + nd;
            if (gn >= n) break;
            float accA = 0.f, accM = 0.f;
#pragma unroll
            for (int d = 0; d < 16; d++) {
                float wa = ma[(h * 16 + d) * 16 + eo];
                float wm = mm[(h * 16 + d) * 16 + eo];
                accA += ks[nd][h * 16 + d] * wa;
                accM += vs[nd][h * 16 + d] * wm;
            }
            size_t ob = ((size_t)r * n + gn) * 128 + c;
            krel[ob] = accA;
            vrel[ob] = accM;
        }
    }
}

// ---------------- pass C: per-edge attention logits + segment max ---------
__global__ __launch_bounds__(256) void attn_kernel(
    const int* __restrict__ src_idx, const int* __restrict__ dst_idx,
    const int* __restrict__ etype, const float* __restrict__ krel,
    const float* __restrict__ q, const float* __restrict__ rel_pri,
    float* __restrict__ att, unsigned* __restrict__ mseg, int n, int e)
{
    int gw = (int)(((size_t)blockIdx.x * blockDim.x + threadIdx.x) >> 5);
    int lane = threadIdx.x & 31;
    if (gw >= e) return;
    int s = src_idx[gw], d = dst_idx[gw], r = etype[gw];
    float4 a = ((const float4*)(krel + ((size_t)r * n + s) * 128))[lane];
    float4 b = ((const float4*)(q + (size_t)d * 128))[lane];
    float p = a.x * b.x + a.y * b.y + a.z * b.z + a.w * b.w;
    p += __shfl_xor_sync(0xFFFFFFFFu, p, 1);
    p += __shfl_xor_sync(0xFFFFFFFFu, p, 2);
    if ((lane & 3) == 0) {
        int h = lane >> 2;
        float val = p * rel_pri[r * kH + h] * 0.25f;  // 1/sqrt(DK)=0.25
        att[(size_t)gw * kH + h] = val;
        atomicMax(&mseg[((size_t)d * kR + r) * kH + h], enc_f(val));
    }
}

// ---------------- pass D: exp + denominator --------------------------------
__global__ __launch_bounds__(256) void exp_den_kernel(
    const int* __restrict__ dst_idx, const int* __restrict__ etype,
    const unsigned* __restrict__ mseg, float* __restrict__ att,
    float* __restrict__ den, int e)
{
    size_t i = (size_t)blockIdx.x * blockDim.x + threadIdx.x;
    if (i >= (size_t)e * kH) return;
    int ed = (int)(i >> 3), h = (int)(i & 7);
    int d = dst_idx[ed], r = etype[ed];
    size_t seg = ((size_t)d * kR + r) * kH + h;
    float m = dec_f(mseg[seg]);
    float ex = expf(att[i] - m);
    att[i] = ex;
    atomicAdd(&den[seg], ex);
}

// ---------------- n_rel^-1 per node ---------------------------------------
__global__ void nrel_kernel(const float* __restrict__ den, float* __restrict__ ninv, int n) {
    int i = blockIdx.x * blockDim.x + threadIdx.x;
    if (i >= n) return;
    int cnt = 0;
#pragma unroll
    for (int r = 0; r < kR; r++)
        cnt += (den[((size_t)i * kR + r) * kH] > 0.f) ? 1 : 0;
    ninv[i] = 1.f / (float)max(cnt, 1);
}

// ---------------- pass E: weighted scatter of vrel into t -----------------
__global__ __launch_bounds__(256) void scatter_kernel(
    const int* __restrict__ src_idx, const int* __restrict__ dst_idx,
    const int* __restrict__ etype, const float* __restrict__ vrel,
    const float* __restrict__ att, const float* __restrict__ den,
    const float* __restrict__ ninv, float* __restrict__ t, int n, int e)
{
    int gw = (int)(((size_t)blockIdx.x * blockDim.x + threadIdx.x) >> 5);
    int lane = threadIdx.x & 31;
    if (gw >= e) return;
    int s = src_idx[gw], d = dst_idx[gw], r = etype[gw];
    int h = lane >> 2;
    float ex = att[(size_t)gw * kH + h];
    float dn = den[((size_t)d * kR + r) * kH + h];
    float w = ex / dn * ninv[d];
    float4 vv = ((const float4*)(vrel + ((size_t)r * n + s) * 128))[lane];
    vv.x *= w; vv.y *= w; vv.z *= w; vv.w *= w;
    red_add_v4(t + (size_t)d * 128 + lane * 4, vv);
}

// ---------------- launch ---------------------------------------------------
extern "C" void kernel_launch(void* const* d_in, const int* in_sizes, int n_in,
                              void* d_out, int out_size) {
    const float* src_h   = (const float*)d_in[0];
    const float* dst_h   = (const float*)d_in[1];
    const float* Wk      = (const float*)d_in[2];
    const float* bk      = (const float*)d_in[3];
    const float* Wq      = (const float*)d_in[4];
    const float* bq      = (const float*)d_in[5];
    const float* Wv      = (const float*)d_in[6];
    const float* bv      = (const float*)d_in[7];
    const float* Wa      = (const float*)d_in[8];
    const float* ba      = (const float*)d_in[9];
    const float* rel_pri = (const float*)d_in[10];
    const float* rel_att = (const float*)d_in[11];
    const float* rel_msg = (const float*)d_in[12];
    const float* skip    = (const float*)d_in[13];
    const int* src_idx   = (const int*)d_in[14];
    const int* dst_idx   = (const int*)d_in[15];
    const int* etype     = (const int*)d_in[16];
    float* out = (float*)d_out;

    int n = in_sizes[0] / kD;
    int e = in_sizes[14];

    float* pool = nullptr;
    cudaGetSymbolAddress((void**)&pool, g_pool);
    float* pq    = pool + OFF_Q;
    float* pk    = pool + OFF_K;
    float* pv    = pool + OFF_V;
    float* pt    = pool + OFF_T;
    float* patt  = pool + OFF_ATT;
    float* pden  = pool + OFF_DEN;
    unsigned* pm = (unsigned*)(pool + OFF_M);
    float* pninv = pool + OFF_NINV;
    float* pkrel = pool + OFF_KREL;
    float* pvrel = pool + OFF_VREL;

    int gemm_blocks = (n + 127) / 128;
    int edge_warp_blocks = (e + 7) / 8;          // 8 warps (256 thr) per block
    int eh_blocks = ((size_t)e * kH + 255) / 256;

    zero_kernel<<<(6400000 + 255) / 256, 256>>>(pt, pden);
    gemm_out128<<<gemm_blocks, 256>>>(dst_h, Wq, bq, nullptr, nullptr, pq, n, 0);
    gemm_out128<<<gemm_blocks, 256>>>(src_h, Wk, bk, nullptr, nullptr, pk, n, 0);
    gemm_out128<<<gemm_blocks, 256>>>(src_h, Wv, bv, nullptr, nullptr, pv, n, 0);
    rel_transform<<<(n + RT_TILE - 1) / RT_TILE, 256>>>(pk, pv, rel_att, rel_msg,
                                                        pkrel, pvrel, n);
    attn_kernel<<<edge_warp_blocks, 256>>>(src_idx, dst_idx, etype, pkrel, pq,
                                           rel_pri, patt, pm, n, e);
    exp_den_kernel<<<eh_blocks, 256>>>(dst_idx, etype, pm, patt, pden, e);
    nrel_kernel<<<(n + 255) / 256, 256>>>(pden, pninv, n);
    scatter_kernel<<<edge_warp_blocks, 256>>>(src_idx, dst_idx, etype, pvrel,
                                              patt, pden, pninv, pt, n, e);
    gemm_out128<<<gemm_blocks, 256>>>(pt, Wa, ba, dst_h, skip, out, n, 1);
}

// round 3
// speedup vs baseline: 1.3530x; 1.3530x over previous
#include <cuda_runtime.h>
#include <cstdint>

// Problem constants
#define kR 8
#define kH 8
#define kDK 16
#define kD 128   // IN_DIM == OUT_DIM

// ---------------- scratch layout (single __device__ pool, float units) ----
//  q     @ 0            (6.4M)
//  k     @ 6.4M         (6.4M)
//  v     @ 12.8M        (6.4M)
//  t     @ 19.2M        (6.4M)
//  krel  @ 25.6M        (51.2M)  [R,N,128]
//  vrel  @ 76.8M        (51.2M)
//  cnt   @ 128.0M       (400001 u32)  segment counts -> starts
//  cur   @ 128.5M       (400001 u32)  scatter cursors
//  bsum  @ 129.0M       (1024 u32)
//  ssrc  @ 129.1M       (1.6M i32)    sorted src indices
#define OFF_Q    0ull
#define OFF_K    6400000ull
#define OFF_V    12800000ull
#define OFF_T    19200000ull
#define OFF_KREL 25600000ull
#define OFF_VREL 76800000ull
#define OFF_CNT  128000000ull
#define OFF_CUR  128500000ull
#define OFF_BSUM 129000000ull
#define OFF_SSRC 129100000ull
#define POOL_SZ  130800000ull

__device__ float g_pool[POOL_SZ];

// ---------------- SIMT sgemm: C[n,128] = A[n,128] @ W[128,128]^T + bias ----
// fuse==1: C = alpha*(AB^T+bias) + (1-alpha)*S,  alpha = sigmoid(skip[0])
__global__ __launch_bounds__(256) void gemm_out128(
    const float* __restrict__ A, const float* __restrict__ W,
    const float* __restrict__ bias, const float* __restrict__ S,
    const float* __restrict__ skipv, float* __restrict__ C,
    int n, int fuse)
{
    __shared__ float As[8][128];
    __shared__ float Bs[8][128];
    int row0 = blockIdx.x * 128;
    int tid = threadIdx.x;
    int tr = (tid >> 4) << 3;
    int tc = (tid & 15) << 3;
    float acc[8][8];
#pragma unroll
    for (int i = 0; i < 8; i++)
#pragma unroll
        for (int j = 0; j < 8; j++) acc[i][j] = 0.f;

    int li = tid >> 1;
    int lk = (tid & 1) << 2;
    for (int k0 = 0; k0 < 128; k0 += 8) {
        float4 a4 = make_float4(0.f, 0.f, 0.f, 0.f);
        if (row0 + li < n)
            a4 = *(const float4*)(A + (size_t)(row0 + li) * 128 + k0 + lk);
        As[lk + 0][li] = a4.x; As[lk + 1][li] = a4.y;
        As[lk + 2][li] = a4.z; As[lk + 3][li] = a4.w;
        float4 b4 = *(const float4*)(W + (size_t)li * 128 + k0 + lk);
        Bs[lk + 0][li] = b4.x; Bs[lk + 1][li] = b4.y;
        Bs[lk + 2][li] = b4.z; Bs[lk + 3][li] = b4.w;
        __syncthreads();
#pragma unroll
        for (int kk = 0; kk < 8; kk++) {
            float ar[8], br[8];
#pragma unroll
            for (int i = 0; i < 8; i++) ar[i] = As[kk][tr + i];
#pragma unroll
            for (int j = 0; j < 8; j++) br[j] = Bs[kk][tc + j];
#pragma unroll
            for (int i = 0; i < 8; i++)
#pragma unroll
                for (int j = 0; j < 8; j++) acc[i][j] += ar[i] * br[j];
        }
        __syncthreads();
    }
    float alpha = 1.f, beta = 0.f;
    if (fuse) {
        float sv = skipv[0];
        alpha = 1.f / (1.f + expf(-sv));
        beta = 1.f - alpha;
    }
#pragma unroll
    for (int i = 0; i < 8; i++) {
        int r = row0 + tr + i;
        if (r >= n) break;
#pragma unroll
        for (int j = 0; j < 8; j++) {
            int c = tc + j;
            float val = acc[i][j] + bias[c];
            if (fuse) val = alpha * val + beta * S[(size_t)r * 128 + c];
            C[(size_t)r * 128 + c] = val;
        }
    }
}

// ---------------- relation transforms: krel/vrel [R,N,128] ----------------
#define RT_TILE 32
__global__ __launch_bounds__(256) void rel_transform(
    const float* __restrict__ k, const float* __restrict__ v,
    const float* __restrict__ ratt, const float* __restrict__ rmsg,
    float* __restrict__ krel, float* __restrict__ vrel, int n)
{
    __shared__ float ks[RT_TILE][128];
    __shared__ float vs[RT_TILE][128];
    __shared__ float ma[2048];
    __shared__ float mm[2048];
    int node0 = blockIdx.x * RT_TILE;
    int tid = threadIdx.x;
    for (int i = tid; i < RT_TILE * 32; i += 256) {
        int nd = i >> 5, c4 = i & 31;
        if (node0 + nd < n) {
            ((float4*)ks[nd])[c4] = ((const float4*)(k + (size_t)(node0 + nd) * 128))[c4];
            ((float4*)vs[nd])[c4] = ((const float4*)(v + (size_t)(node0 + nd) * 128))[c4];
        }
    }
    int c = tid & 127;
    int half = tid >> 7;
    int h = c >> 4, eo = c & 15;
    for (int r = 0; r < kR; r++) {
        __syncthreads();
        for (int i = tid; i < 2048; i += 256) {
            ma[i] = ratt[r * 2048 + i];
            mm[i] = rmsg[r * 2048 + i];
        }
        __syncthreads();
        for (int nd = half; nd < RT_TILE; nd += 2) {
            int gn = node0 + nd;
            if (gn >= n) break;
            float accA = 0.f, accM = 0.f;
#pragma unroll
            for (int d = 0; d < 16; d++) {
                float wa = ma[(h * 16 + d) * 16 + eo];
                float wm = mm[(h * 16 + d) * 16 + eo];
                accA += ks[nd][h * 16 + d] * wa;
                accM += vs[nd][h * 16 + d] * wm;
            }
            size_t ob = ((size_t)r * n + gn) * 128 + c;
            krel[ob] = accA;
            vrel[ob] = accM;
        }
    }
}

// ---------------- counting sort by seg = dst*8 + etype --------------------
__global__ void zero_cnt(unsigned* __restrict__ cnt, int nseg) {
    int i = blockIdx.x * blockDim.x + threadIdx.x;
    if (i <= nseg) cnt[i] = 0u;
}

__global__ void hist_kernel(const int* __restrict__ dst, const int* __restrict__ et,
                            unsigned* __restrict__ cnt, int e) {
    int i = blockIdx.x * blockDim.x + threadIdx.x;
    if (i < e) atomicAdd(&cnt[dst[i] * kR + et[i]], 1u);
}

__global__ __launch_bounds__(1024) void scan_local(
    const unsigned* __restrict__ cnt, unsigned* __restrict__ starts,
    unsigned* __restrict__ bsum, int nseg)
{
    __shared__ unsigned sm[1024];
    int tid = threadIdx.x;
    int g = blockIdx.x * 1024 + tid;
    unsigned x = (g < nseg) ? cnt[g] : 0u;
    sm[tid] = x; __syncthreads();
    for (int off = 1; off < 1024; off <<= 1) {
        unsigned val = sm[tid];
        if (tid >= off) val += sm[tid - off];
        __syncthreads(); sm[tid] = val; __syncthreads();
    }
    if (g < nseg) starts[g] = sm[tid] - x;     // local exclusive
    if (tid == 1023) bsum[blockIdx.x] = sm[1023];
}

__global__ __launch_bounds__(1024) void scan_block(unsigned* __restrict__ bsum, int nb) {
    __shared__ unsigned sm[1024];
    int tid = threadIdx.x;
    unsigned x = (tid < nb) ? bsum[tid] : 0u;
    sm[tid] = x; __syncthreads();
    for (int off = 1; off < 1024; off <<= 1) {
        unsigned val = sm[tid];
        if (tid >= off) val += sm[tid - off];
        __syncthreads(); sm[tid] = val; __syncthreads();
    }
    if (tid < nb) bsum[tid] = sm[tid] - x;     // exclusive
}

__global__ void scan_add(unsigned* __restrict__ starts, unsigned* __restrict__ cur,
                         const unsigned* __restrict__ bsum, int nseg, int e) {
    int g = blockIdx.x * 1024 + threadIdx.x;
    if (g < nseg) {
        unsigned v = starts[g] + bsum[blockIdx.x];
        starts[g] = v;
        cur[g] = v;
    }
    if (g == 0) starts[nseg] = (unsigned)e;
}

__global__ void permute_kernel(const int* __restrict__ src, const int* __restrict__ dst,
                               const int* __restrict__ et, unsigned* __restrict__ cur,
                               int* __restrict__ ssrc, int e) {
    int i = blockIdx.x * blockDim.x + threadIdx.x;
    if (i >= e) return;
    int sg = dst[i] * kR + et[i];
    unsigned pos = atomicAdd(&cur[sg], 1u);
    ssrc[pos] = src[i];
}

// ---------------- fused: online softmax + message aggregation -------------
// one warp per dst node; edges sorted by (dst, rel) are contiguous.
__global__ __launch_bounds__(256) void fused_edge(
    const unsigned* __restrict__ starts, const int* __restrict__ ssrc,
    const float* __restrict__ krel, const float* __restrict__ vrel,
    const float* __restrict__ q, const float* __restrict__ rel_pri,
    float* __restrict__ t, int n)
{
    int d = (int)(((size_t)blockIdx.x * blockDim.x + threadIdx.x) >> 5);
    int lane = threadIdx.x & 31;
    if (d >= n) return;
    int h = lane >> 2;

    float4 qv = ((const float4*)(q + (size_t)d * 128))[lane];
    float4 tacc = make_float4(0.f, 0.f, 0.f, 0.f);
    int nrel = 0;
    unsigned base = (unsigned)d * kR;

    for (int r = 0; r < kR; r++) {
        unsigned s0 = starts[base + r];
        unsigned s1 = starts[base + r + 1];
        if (s0 == s1) continue;
        nrel++;
        float pri = rel_pri[r * kH + h] * 0.25f;   // includes 1/sqrt(DK)
        const float* kb = krel + (size_t)r * n * 128;
        const float* vb = vrel + (size_t)r * n * 128;

        float m = -1e30f, ssum = 0.f;
        float4 acc = make_float4(0.f, 0.f, 0.f, 0.f);

        // software-pipelined gather
        int src = ssrc[s0];
        float4 kv = ((const float4*)(kb + (size_t)src * 128))[lane];
        float4 vv = ((const float4*)(vb + (size_t)src * 128))[lane];
        for (unsigned i = s0; i < s1; i++) {
            float4 ckv = kv, cvv = vv;
            if (i + 1 < s1) {
                int ns = ssrc[i + 1];
                kv = ((const float4*)(kb + (size_t)ns * 128))[lane];
                vv = ((const float4*)(vb + (size_t)ns * 128))[lane];
            }
            float p = ckv.x * qv.x + ckv.y * qv.y + ckv.z * qv.z + ckv.w * qv.w;
            p += __shfl_xor_sync(0xFFFFFFFFu, p, 1);
            p += __shfl_xor_sync(0xFFFFFFFFu, p, 2);
            float a = p * pri;
            float nm = fmaxf(m, a);
            float scale = __expf(m - nm);      // first iter: exp(-huge) = 0
            float w = __expf(a - nm);
            ssum = ssum * scale + w;
            acc.x = acc.x * scale + w * cvv.x;
            acc.y = acc.y * scale + w * cvv.y;
            acc.z = acc.z * scale + w * cvv.z;
            acc.w = acc.w * scale + w * cvv.w;
            m = nm;
        }
        float inv = 1.f / ssum;
        tacc.x += acc.x * inv;
        tacc.y += acc.y * inv;
        tacc.z += acc.z * inv;
        tacc.w += acc.w * inv;
    }
    float ninv = 1.f / (float)max(nrel, 1);
    ((float4*)(t + (size_t)d * 128))[lane] =
        make_float4(tacc.x * ninv, tacc.y * ninv, tacc.z * ninv, tacc.w * ninv);
}

// ---------------- launch ---------------------------------------------------
extern "C" void kernel_launch(void* const* d_in, const int* in_sizes, int n_in,
                              void* d_out, int out_size) {
    const float* src_h   = (const float*)d_in[0];
    const float* dst_h   = (const float*)d_in[1];
    const float* Wk      = (const float*)d_in[2];
    const float* bk      = (const float*)d_in[3];
    const float* Wq      = (const float*)d_in[4];
    const float* bq      = (const float*)d_in[5];
    const float* Wv      = (const float*)d_in[6];
    const float* bv      = (const float*)d_in[7];
    const float* Wa      = (const float*)d_in[8];
    const float* ba      = (const float*)d_in[9];
    const float* rel_pri = (const float*)d_in[10];
    const float* rel_att = (const float*)d_in[11];
    const float* rel_msg = (const float*)d_in[12];
    const float* skip    = (const float*)d_in[13];
    const int* src_idx   = (const int*)d_in[14];
    const int* dst_idx   = (const int*)d_in[15];
    const int* etype     = (const int*)d_in[16];
    float* out = (float*)d_out;

    int n = in_sizes[0] / kD;
    int e = in_sizes[14];
    int nseg = n * kR;

    float* pool = nullptr;
    cudaGetSymbolAddress((void**)&pool, g_pool);
    float* pq    = pool + OFF_Q;
    float* pk    = pool + OFF_K;
    float* pv    = pool + OFF_V;
    float* pt    = pool + OFF_T;
    float* pkrel = pool + OFF_KREL;
    float* pvrel = pool + OFF_VREL;
    unsigned* pcnt  = (unsigned*)(pool + OFF_CNT);
    unsigned* pcur  = (unsigned*)(pool + OFF_CUR);
    unsigned* pbsum = (unsigned*)(pool + OFF_BSUM);
    int* pssrc      = (int*)(pool + OFF_SSRC);

    int gemm_blocks = (n + 127) / 128;
    int nb = (nseg + 1023) / 1024;

    // counting sort by (dst, rel)
    zero_cnt<<<(nseg + 256) / 256, 256>>>(pcnt, nseg);
    hist_kernel<<<(e + 255) / 256, 256>>>(dst_idx, etype, pcnt, e);
    scan_local<<<nb, 1024>>>(pcnt, pcnt /*in-place ok: read then write same idx*/, pbsum, nseg);
    scan_block<<<1, 1024>>>(pbsum, nb);
    scan_add<<<nb, 1024>>>(pcnt, pcur, pbsum, nseg, e);
    permute_kernel<<<(e + 255) / 256, 256>>>(src_idx, dst_idx, etype, pcur, pssrc, e);

    // projections + relation transforms
    gemm_out128<<<gemm_blocks, 256>>>(dst_h, Wq, bq, nullptr, nullptr, pq, n, 0);
    gemm_out128<<<gemm_blocks, 256>>>(src_h, Wk, bk, nullptr, nullptr, pk, n, 0);
    gemm_out128<<<gemm_blocks, 256>>>(src_h, Wv, bv, nullptr, nullptr, pv, n, 0);
    rel_transform<<<(n + RT_TILE - 1) / RT_TILE, 256>>>(pk, pv, rel_att, rel_msg,
                                                        pkrel, pvrel, n);

    // fused attention + softmax + aggregation (no atomics)
    fused_edge<<<((size_t)n * 32 + 255) / 256, 256>>>(pcnt, pssrc, pkrel, pvrel,
                                                      pq, rel_pri, pt, n);

    // output projection + skip
    gemm_out128<<<gemm_blocks, 256>>>(pt, Wa, ba, dst_h, skip, out, n, 1);
}

// round 5
// speedup vs baseline: 1.5521x; 1.1472x over previous
#include <cuda_runtime.h>
#include <cuda_fp16.h>
#include <cstdint>

// Problem constants
#define kR 8
#define kH 8
#define kDK 16
#define kD 128   // IN_DIM == OUT_DIM

// ---------------- scratch layout (single __device__ pool, float units) ----
//  q      @ 0          (6.4M f32)
//  k      @ 6.4M       (6.4M f32)
//  v      @ 12.8M      (6.4M f32)
//  t      @ 19.2M      (6.4M f32)
//  krel_h @ 25.6M      (51.2M half = 25.6M f32)   [R,N,128] fp16
//  vrel_h @ 51.2M      (51.2M half = 25.6M f32)
//  cnt    @ 76.8M      (400001 u32)
//  cur    @ 77.3M      (400001 u32)
//  bsum   @ 77.8M      (1024 u32)
//  ssrc   @ 77.81M     (1.6M i32)
#define OFF_Q     0ull
#define OFF_K     6400000ull
#define OFF_V     12800000ull
#define OFF_T     19200000ull
#define OFF_KRELH 25600000ull
#define OFF_VRELH 51200000ull
#define OFF_CNT   76800000ull
#define OFF_CUR   77300000ull
#define OFF_BSUM  77800000ull
#define OFF_SSRC  77810000ull
#define POOL_SZ   79500000ull

__device__ float g_pool[POOL_SZ];

// ---------------- SIMT sgemm: C[n,128] = A[n,128] @ W[128,128]^T + bias ----
// fuse==1: C = alpha*(AB^T+bias) + (1-alpha)*S,  alpha = sigmoid(skip[0])
__global__ __launch_bounds__(256) void gemm_out128(
    const float* __restrict__ A, const float* __restrict__ W,
    const float* __restrict__ bias, const float* __restrict__ S,
    const float* __restrict__ skipv, float* __restrict__ C,
    int n, int fuse)
{
    __shared__ float As[8][128];
    __shared__ float Bs[8][128];
    int row0 = blockIdx.x * 128;
    int tid = threadIdx.x;
    int tr = (tid >> 4) << 3;
    int tc = (tid & 15) << 3;
    float acc[8][8];
#pragma unroll
    for (int i = 0; i < 8; i++)
#pragma unroll
        for (int j = 0; j < 8; j++) acc[i][j] = 0.f;

    int li = tid >> 1;
    int lk = (tid & 1) << 2;
    for (int k0 = 0; k0 < 128; k0 += 8) {
        float4 a4 = make_float4(0.f, 0.f, 0.f, 0.f);
        if (row0 + li < n)
            a4 = *(const float4*)(A + (size_t)(row0 + li) * 128 + k0 + lk);
        As[lk + 0][li] = a4.x; As[lk + 1][li] = a4.y;
        As[lk + 2][li] = a4.z; As[lk + 3][li] = a4.w;
        float4 b4 = *(const float4*)(W + (size_t)li * 128 + k0 + lk);
        Bs[lk + 0][li] = b4.x; Bs[lk + 1][li] = b4.y;
        Bs[lk + 2][li] = b4.z; Bs[lk + 3][li] = b4.w;
        __syncthreads();
#pragma unroll
        for (int kk = 0; kk < 8; kk++) {
            float ar[8], br[8];
#pragma unroll
            for (int i = 0; i < 8; i++) ar[i] = As[kk][tr + i];
#pragma unroll
            for (int j = 0; j < 8; j++) br[j] = Bs[kk][tc + j];
#pragma unroll
            for (int i = 0; i < 8; i++)
#pragma unroll
                for (int j = 0; j < 8; j++) acc[i][j] += ar[i] * br[j];
        }
        __syncthreads();
    }
    float alpha = 1.f, beta = 0.f;
    if (fuse) {
        float sv = skipv[0];
        alpha = 1.f / (1.f + expf(-sv));
        beta = 1.f - alpha;
    }
#pragma unroll
    for (int i = 0; i < 8; i++) {
        int r = row0 + tr + i;
        if (r >= n) break;
#pragma unroll
        for (int j = 0; j < 8; j++) {
            int c = tc + j;
            float val = acc[i][j] + bias[c];
            if (fuse) val = alpha * val + beta * S[(size_t)r * 128 + c];
            C[(size_t)r * 128 + c] = val;
        }
    }
}

// ---------------- relation transforms -> fp16 krel/vrel [R,N,128] ---------
#define RT_TILE 32
__global__ __launch_bounds__(256) void rel_transform_h(
    const float* __restrict__ k, const float* __restrict__ v,
    const float* __restrict__ ratt, const float* __restrict__ rmsg,
    __half2* __restrict__ krel, __half2* __restrict__ vrel, int n)
{
    __shared__ float ks[RT_TILE][128];
    __shared__ float vs[RT_TILE][128];
    __shared__ float ma[2048];
    __shared__ float mm[2048];
    int node0 = blockIdx.x * RT_TILE;
    int tid = threadIdx.x;
    for (int i = tid; i < RT_TILE * 32; i += 256) {
        int nd = i >> 5, c4 = i & 31;
        if (node0 + nd < n) {
            ((float4*)ks[nd])[c4] = ((const float4*)(k + (size_t)(node0 + nd) * 128))[c4];
            ((float4*)vs[nd])[c4] = ((const float4*)(v + (size_t)(node0 + nd) * 128))[c4];
        }
    }
    int cp = tid & 63;      // half2 column index 0..63
    int c0 = cp << 1;       // even component
    int h = c0 >> 4;
    int e0 = c0 & 15;
    int nsub = tid >> 6;    // 0..3
    for (int r = 0; r < kR; r++) {
        __syncthreads();
        for (int i = tid; i < 2048; i += 256) {
            ma[i] = ratt[r * 2048 + i];
            mm[i] = rmsg[r * 2048 + i];
        }
        __syncthreads();
        for (int nd = nsub; nd < RT_TILE; nd += 4) {
            int gn = node0 + nd;
            if (gn >= n) break;
            float a0 = 0.f, a1 = 0.f, m0 = 0.f, m1 = 0.f;
#pragma unroll
            for (int d = 0; d < 16; d++) {
                float kk = ks[nd][h * 16 + d];
                float vv = vs[nd][h * 16 + d];
                int mi = (h * 16 + d) * 16 + e0;
                a0 += kk * ma[mi];     a1 += kk * ma[mi + 1];
                m0 += vv * mm[mi];     m1 += vv * mm[mi + 1];
            }
            size_t ob = ((size_t)r * n + gn) * 64 + cp;
            krel[ob] = __floats2half2_rn(a0, a1);
            vrel[ob] = __floats2half2_rn(m0, m1);
        }
    }
}

// ---------------- counting sort by seg = dst*8 + etype --------------------
__global__ void zero_cnt(unsigned* __restrict__ cnt, int nseg) {
    int i = blockIdx.x * blockDim.x + threadIdx.x;
    if (i <= nseg) cnt[i] = 0u;
}

__global__ void hist_kernel(const int* __restrict__ dst, const int* __restrict__ et,
                            unsigned* __restrict__ cnt, int e) {
    int i = blockIdx.x * blockDim.x + threadIdx.x;
    if (i < e) atomicAdd(&cnt[dst[i] * kR + et[i]], 1u);
}

__global__ __launch_bounds__(1024) void scan_local(
    const unsigned* __restrict__ cnt, unsigned* __restrict__ starts,
    unsigned* __restrict__ bsum, int nseg)
{
    __shared__ unsigned sm[1024];
    int tid = threadIdx.x;
    int g = blockIdx.x * 1024 + tid;
    unsigned x = (g < nseg) ? cnt[g] : 0u;
    sm[tid] = x; __syncthreads();
    for (int off = 1; off < 1024; off <<= 1) {
        unsigned val = sm[tid];
        if (tid >= off) val += sm[tid - off];
        __syncthreads(); sm[tid] = val; __syncthreads();
    }
    if (g < nseg) starts[g] = sm[tid] - x;
    if (tid == 1023) bsum[blockIdx.x] = sm[1023];
}

__global__ __launch_bounds__(1024) void scan_block(unsigned* __restrict__ bsum, int nb) {
    __shared__ unsigned sm[1024];
    int tid = threadIdx.x;
    unsigned x = (tid < nb) ? bsum[tid] : 0u;
    sm[tid] = x; __syncthreads();
    for (int off = 1; off < 1024; off <<= 1) {
        unsigned val = sm[tid];
        if (tid >= off) val += sm[tid - off];
        __syncthreads(); sm[tid] = val; __syncthreads();
    }
    if (tid < nb) bsum[tid] = sm[tid] - x;
}

__global__ void scan_add(unsigned* __restrict__ starts, unsigned* __restrict__ cur,
                         const unsigned* __restrict__ bsum, int nseg, int e) {
    int g = blockIdx.x * 1024 + threadIdx.x;
    if (g < nseg) {
        unsigned v = starts[g] + bsum[blockIdx.x];
        starts[g] = v;
        cur[g] = v;
    }
    if (g == 0) starts[nseg] = (unsigned)e;
}

__global__ void permute_kernel(const int* __restrict__ src, const int* __restrict__ dst,
                               const int* __restrict__ et, unsigned* __restrict__ cur,
                               int* __restrict__ ssrc, int e) {
    int i = blockIdx.x * blockDim.x + threadIdx.x;
    if (i >= e) return;
    int sg = dst[i] * kR + et[i];
    unsigned pos = atomicAdd(&cur[sg], 1u);
    ssrc[pos] = src[i];
}

// ---------------- fused: online softmax + aggregation (fp16 gather) -------
__global__ __launch_bounds__(256) void fused_edge_h(
    const unsigned* __restrict__ starts, const int* __restrict__ ssrc,
    const __half2* __restrict__ krel, const __half2* __restrict__ vrel,
    const float* __restrict__ q, const float* __restrict__ rel_pri,
    float* __restrict__ t, int n)
{
    int d = (int)(((size_t)blockIdx.x * blockDim.x + threadIdx.x) >> 5);
    int lane = threadIdx.x & 31;
    if (d >= n) return;
    int h = lane >> 2;

    float4 qv = ((const float4*)(q + (size_t)d * 128))[lane];
    float4 tacc = make_float4(0.f, 0.f, 0.f, 0.f);
    int nrel = 0;
    unsigned base = (unsigned)d * kR;

    for (int r = 0; r < kR; r++) {
        unsigned s0 = starts[base + r];
        unsigned s1 = starts[base + r + 1];
        if (s0 == s1) continue;
        nrel++;
        float pri = rel_pri[r * kH + h] * 0.25f;
        const __half2* kb = krel + (size_t)r * n * 64;
        const __half2* vb = vrel + (size_t)r * n * 64;

        float m = -1e30f, ssum = 0.f;
        float4 acc = make_float4(0.f, 0.f, 0.f, 0.f);

        int src = ssrc[s0];
        uint2 ku = *(const uint2*)(kb + (size_t)src * 64 + lane * 2);
        uint2 vu = *(const uint2*)(vb + (size_t)src * 64 + lane * 2);
        for (unsigned i = s0; i < s1; i++) {
            uint2 cku = ku, cvu = vu;
            if (i + 1 < s1) {
                int ns = ssrc[i + 1];
                ku = *(const uint2*)(kb + (size_t)ns * 64 + lane * 2);
                vu = *(const uint2*)(vb + (size_t)ns * 64 + lane * 2);
            }
            float2 k01 = __half22float2(*(__half2*)&cku.x);
            float2 k23 = __half22float2(*(__half2*)&cku.y);
            float p = k01.x * qv.x + k01.y * qv.y + k23.x * qv.z + k23.y * qv.w;
            p += __shfl_xor_sync(0xFFFFFFFFu, p, 1);
            p += __shfl_xor_sync(0xFFFFFFFFu, p, 2);
            float a = p * pri;
            float nm = fmaxf(m, a);
            float scale = __expf(m - nm);
            float w = __expf(a - nm);
            float2 v01 = __half22float2(*(__half2*)&cvu.x);
            float2 v23 = __half22float2(*(__half2*)&cvu.y);
            ssum = ssum * scale + w;
            acc.x = acc.x * scale + w * v01.x;
            acc.y = acc.y * scale + w * v01.y;
            acc.z = acc.z * scale + w * v23.x;
            acc.w = acc.w * scale + w * v23.y;
            m = nm;
        }
        float inv = 1.f / ssum;
        tacc.x += acc.x * inv;
        tacc.y += acc.y * inv;
        tacc.z += acc.z * inv;
        tacc.w += acc.w * inv;
    }
    float ninv = 1.f / (float)max(nrel, 1);
    ((float4*)(t + (size_t)d * 128))[lane] =
        make_float4(tacc.x * ninv, tacc.y * ninv, tacc.z * ninv, tacc.w * ninv);
}

// ---------------- launch ---------------------------------------------------
extern "C" void kernel_launch(void* const* d_in, const int* in_sizes, int n_in,
                              void* d_out, int out_size) {
    const float* src_h   = (const float*)d_in[0];
    const float* dst_h   = (const float*)d_in[1];
    const float* Wk      = (const float*)d_in[2];
    const float* bk      = (const float*)d_in[3];
    const float* Wq      = (const float*)d_in[4];
    const float* bq      = (const float*)d_in[5];
    const float* Wv      = (const float*)d_in[6];
    const float* bv      = (const float*)d_in[7];
    const float* Wa      = (const float*)d_in[8];
    const float* ba      = (const float*)d_in[9];
    const float* rel_pri = (const float*)d_in[10];
    const float* rel_att = (const float*)d_in[11];
    const float* rel_msg = (const float*)d_in[12];
    const float* skip    = (const float*)d_in[13];
    const int* src_idx   = (const int*)d_in[14];
    const int* dst_idx   = (const int*)d_in[15];
    const int* etype     = (const int*)d_in[16];
    float* out = (float*)d_out;

    int n = in_sizes[0] / kD;
    int e = in_sizes[14];
    int nseg = n * kR;

    float* pool = nullptr;
    cudaGetSymbolAddress((void**)&pool, g_pool);
    float* pq    = pool + OFF_Q;
    float* pk    = pool + OFF_K;
    float* pv    = pool + OFF_V;
    float* pt    = pool + OFF_T;
    __half2* pkrel = (__half2*)(pool + OFF_KRELH);
    __half2* pvrel = (__half2*)(pool + OFF_VRELH);
    unsigned* pcnt  = (unsigned*)(pool + OFF_CNT);
    unsigned* pcur  = (unsigned*)(pool + OFF_CUR);
    unsigned* pbsum = (unsigned*)(pool + OFF_BSUM);
    int* pssrc      = (int*)(pool + OFF_SSRC);

    int gemm_blocks = (n + 127) / 128;
    int nb = (nseg + 1023) / 1024;

    // counting sort by (dst, rel)
    zero_cnt<<<(nseg + 256) / 256, 256>>>(pcnt, nseg);
    hist_kernel<<<(e + 255) / 256, 256>>>(dst_idx, etype, pcnt, e);
    scan_local<<<nb, 1024>>>(pcnt, pcnt, pbsum, nseg);
    scan_block<<<1, 1024>>>(pbsum, nb);
    scan_add<<<nb, 1024>>>(pcnt, pcur, pbsum, nseg, e);
    permute_kernel<<<(e + 255) / 256, 256>>>(src_idx, dst_idx, etype, pcur, pssrc, e);

    // projections + relation transforms (fp16 out)
    gemm_out128<<<gemm_blocks, 256>>>(dst_h, Wq, bq, nullptr, nullptr, pq, n, 0);
    gemm_out128<<<gemm_blocks, 256>>>(src_h, Wk, bk, nullptr, nullptr, pk, n, 0);
    gemm_out128<<<gemm_blocks, 256>>>(src_h, Wv, bv, nullptr, nullptr, pv, n, 0);
    rel_transform_h<<<(n + RT_TILE - 1) / RT_TILE, 256>>>(pk, pv, rel_att, rel_msg,
                                                          pkrel, pvrel, n);

    // fused attention + softmax + aggregation
    fused_edge_h<<<((size_t)n * 32 + 255) / 256, 256>>>(pcnt, pssrc, pkrel, pvrel,
                                                        pq, rel_pri, pt, n);

    // output projection + skip
    gemm_out128<<<gemm_blocks, 256>>>(pt, Wa, ba, dst_h, skip, out, n, 1);
}